// round 14
// baseline (speedup 1.0000x reference)
#include <cuda_runtime.h>
#include <cuda_bf16.h>
#include <cuda_fp16.h>
#include <cstdint>

// ============================================================================
// NonLocalPositionAttention
//   y = alpha * (x @ softmax(e1^T e2)^T) + relu(w3 @ x + b3)
// alpha == 0 for benchmark inputs -> y == relu(w3 @ x + b3).
// Assembly GEMM: mma.sync m16n8k16 fp16 (fp32 acc). R14 = R12 (64x64 warp
// tiles, 4 warps/CTA, 3-stage cp.async, 3 CTAs/SM) + anti-phase warp
// scheduling: odd-wn warps traverse k-steps in reverse, odd-wm warps reverse
// the mi loop, so LDS bursts of half the warps overlap MMA bursts of the
// other half instead of phase-locking on the port. Attention branch guarded.
// ============================================================================

#define NB   4
#define CCH  2048
#define DCH  256
#define HWP  4096

// ---- scratch ---------------------------------------------------------------
__device__ float  g_e1[(size_t)NB * DCH * HWP];
__device__ float  g_e2[(size_t)NB * DCH * HWP];
__device__ float  g_attn[(size_t)NB * HWP * HWP];
__device__ __half g_w3h[(size_t)CCH * CCH];           // fp16 W3 [o][k]
__device__ __half g_xth[(size_t)NB * HWP * CCH];      // fp16 X^T [n][p][k]

// ============================================================================
// helpers
// ============================================================================
__device__ __forceinline__ uint32_t smem_u32(const void* p) {
    uint32_t a;
    asm("{ .reg .u64 t; cvta.to.shared.u64 t, %1; cvt.u32.u64 %0, t; }"
        : "=r"(a) : "l"(p));
    return a;
}
__device__ __forceinline__ void cp_async16(uint32_t dst, const void* src) {
    asm volatile("cp.async.cg.shared.global [%0], [%1], 16;"
                 :: "r"(dst), "l"(src) : "memory");
}
#define CP_COMMIT() asm volatile("cp.async.commit_group;" ::: "memory")
#define CP_WAIT1()  asm volatile("cp.async.wait_group 1;" ::: "memory")

__device__ __forceinline__ void mma_f16(float* d, const uint32_t* a,
                                        const uint32_t* b) {
    asm volatile(
        "mma.sync.aligned.m16n8k16.row.col.f32.f16.f16.f32 "
        "{%0,%1,%2,%3}, {%4,%5,%6,%7}, {%8,%9}, {%0,%1,%2,%3};"
        : "+f"(d[0]), "+f"(d[1]), "+f"(d[2]), "+f"(d[3])
        : "r"(a[0]), "r"(a[1]), "r"(a[2]), "r"(a[3]), "r"(b[0]), "r"(b[1]));
}

// ============================================================================
// fused pre-pass: z<NB -> X transpose->fp16; z==NB -> W3 ->fp16
// ============================================================================
__global__ void __launch_bounds__(256)
prepass_kernel(const float* __restrict__ x, __half* __restrict__ xt,
               const float4* __restrict__ w3, uint2* __restrict__ w3h)
{
    const int tid = threadIdx.x;
    if (blockIdx.z < NB) {
        __shared__ float t[32][65];   // [p_local][c_local]
        const int n  = blockIdx.z;
        const int c0 = blockIdx.y * 64;
        const int p0 = blockIdx.x * 32;

        const float* xb = x + (size_t)n * CCH * HWP;
        __half* xtb = xt + (size_t)n * HWP * CCH;

        {
            const int p_l = tid & 31;
            #pragma unroll
            for (int i = 0; i < 8; ++i) {
                const int c_l = (tid >> 5) + i * 8;
                t[p_l][c_l] = xb[(size_t)(c0 + c_l) * HWP + p0 + p_l];
            }
        }
        __syncthreads();
        {
            const int cp = tid & 31;
            #pragma unroll
            for (int i = 0; i < 4; ++i) {
                const int p_l = (tid >> 5) + i * 8;
                __half2 v = __floats2half2_rn(t[p_l][2 * cp], t[p_l][2 * cp + 1]);
                *reinterpret_cast<__half2*>(
                    &xtb[(size_t)(p0 + p_l) * CCH + c0 + 2 * cp]) = v;
            }
        }
    } else {
        const int i = (blockIdx.y * 128 + blockIdx.x) * 256 + tid;
        const float4 v = w3[i];
        __half2 lo = __floats2half2_rn(v.x, v.y);
        __half2 hi = __floats2half2_rn(v.z, v.w);
        uint2 o;
        o.x = *reinterpret_cast<uint32_t*>(&lo);
        o.y = *reinterpret_cast<uint32_t*>(&hi);
        w3h[i] = o;
    }
}

// ============================================================================
// fp16 tensor-core GEMM + bias + relu (fp32 accumulate):
//   out[n,o,p] = relu( sum_c W[o,c] * X[n,c,p] + bias[o] )
// CTA tile 128x128x32; 4 warps (2m x 2n), warp tile 64x64.
// Anti-phase: ks order flipped for odd wn, mi direction flipped for odd wm.
// A/B smem rows pitch 20 words (conflict-free). 3-stage ring, 3 CTAs/SM.
// ============================================================================
#define HTM 128
#define HTN 128
#define HTK 32
#define H_NSLABS (CCH / HTK)                 // 64
#define HPITCH_B 80                          // bytes per smem row
#define A_STAGE (HTM * HPITCH_B)             // 10240
#define B_STAGE (HTN * HPITCH_B)             // 10240
#define STAGE_B (A_STAGE + B_STAGE)          // 20480
#define NSTAGE 3
#define GEMM_DSMEM (NSTAGE * STAGE_B)        // 61440

__global__ void __launch_bounds__(128, 3)
gemm_f16_bias_relu(const __half* __restrict__ Wh, const __half* __restrict__ Xth,
                   const float* __restrict__ bias, float* __restrict__ out)
{
    extern __shared__ char smem[];
    const uint32_t smem_base = smem_u32(smem);

    const int tid  = threadIdx.x;
    const int wid  = tid >> 5;
    const int lane = tid & 31;
    const int g    = lane >> 2;
    const int tig  = lane & 3;
    const int wm   = wid >> 1;     // 0..1
    const int wn   = wid & 1;      // 0..1

    const int n  = blockIdx.z;
    const int o0 = blockIdx.y * HTM;
    const int p0 = blockIdx.x * HTN;
    const __half* Xb = Xth + (size_t)n * HWP * CCH;
    float*        Ob = out + (size_t)n * CCH * HWP;

    float acc[4][8][4];
    #pragma unroll
    for (int mi = 0; mi < 4; ++mi)
        #pragma unroll
        for (int ni = 0; ni < 8; ++ni)
            #pragma unroll
            for (int q = 0; q < 4; ++q) acc[mi][ni][q] = 0.0f;

    const int cp_row = tid >> 2, cp_cw = tid & 3;

    #define ISSUE_SLAB(S, BUF) do {                                           \
        const int _k0 = (S) * HTK;                                            \
        const uint32_t _dA = smem_base + (BUF) * STAGE_B;                     \
        const uint32_t _dB = _dA + A_STAGE;                                   \
        _Pragma("unroll")                                                     \
        for (int j = 0; j < 4; ++j) {                                         \
            const int row = cp_row + j * 32;                                  \
            cp_async16(_dA + row * HPITCH_B + cp_cw * 16,                     \
                       &Wh[(size_t)(o0 + row) * CCH + _k0 + cp_cw * 8]);      \
        }                                                                     \
        _Pragma("unroll")                                                     \
        for (int j = 0; j < 4; ++j) {                                         \
            const int row = cp_row + j * 32;                                  \
            cp_async16(_dB + row * HPITCH_B + cp_cw * 16,                     \
                       &Xb[(size_t)(p0 + row) * CCH + _k0 + cp_cw * 8]);      \
        }                                                                     \
    } while (0)

    ISSUE_SLAB(0, 0); CP_COMMIT();
    ISSUE_SLAB(1, 1); CP_COMMIT();

    for (int s = 0; s < H_NSLABS; ++s) {
        CP_WAIT1();
        __syncthreads();
        if (s + 2 < H_NSLABS) ISSUE_SLAB(s + 2, (s + 2) % NSTAGE);
        CP_COMMIT();

        const uint32_t* As = reinterpret_cast<const uint32_t*>(
            smem + (s % NSTAGE) * STAGE_B);
        const uint32_t* Bs = reinterpret_cast<const uint32_t*>(
            smem + (s % NSTAGE) * STAGE_B + A_STAGE);

        #pragma unroll
        for (int ksi = 0; ksi < 2; ++ksi) {
            const int ks = ksi ^ wn;          // odd-wn warps: reverse k order
            const int kw = ks * 8 + tig;      // word index within 20-word row
            uint32_t b[8][2];
            #pragma unroll
            for (int ni = 0; ni < 8; ++ni) {
                const int col = wn * 64 + ni * 8 + g;
                b[ni][0] = Bs[col * 20 + kw];
                b[ni][1] = Bs[col * 20 + kw + 4];
            }
            #pragma unroll
            for (int mii = 0; mii < 4; ++mii) {
                const int mi = wm ? (3 - mii) : mii;  // odd-wm: reverse mi
                const int m = wm * 64 + mi * 16;
                uint32_t a[4];
                a[0] = As[(m + g) * 20 + kw];
                a[1] = As[(m + 8 + g) * 20 + kw];
                a[2] = As[(m + g) * 20 + kw + 4];
                a[3] = As[(m + 8 + g) * 20 + kw + 4];
                #pragma unroll
                for (int ni = 0; ni < 8; ++ni)
                    mma_f16(acc[mi][ni], a, b[ni]);
            }
        }
    }

    // ---- epilogue: bias + relu -> GMEM ----
    #pragma unroll
    for (int mi = 0; mi < 4; ++mi) {
        const int row_lo = o0 + wm * 64 + mi * 16 + g;
        const int row_hi = row_lo + 8;
        const float blo = __ldg(&bias[row_lo]);
        const float bhi = __ldg(&bias[row_hi]);
        float* plo = &Ob[(size_t)row_lo * HWP + p0 + wn * 64 + tig * 2];
        float* phi = &Ob[(size_t)row_hi * HWP + p0 + wn * 64 + tig * 2];
        #pragma unroll
        for (int ni = 0; ni < 8; ++ni) {
            float2 vlo, vhi;
            vlo.x = fmaxf(acc[mi][ni][0] + blo, 0.0f);
            vlo.y = fmaxf(acc[mi][ni][1] + blo, 0.0f);
            vhi.x = fmaxf(acc[mi][ni][2] + bhi, 0.0f);
            vhi.y = fmaxf(acc[mi][ni][3] + bhi, 0.0f);
            *reinterpret_cast<float2*>(&plo[ni * 8]) = vlo;
            *reinterpret_cast<float2*>(&phi[ni * 8]) = vhi;
        }
    }
}

// ============================================================================
// FFMA2 SGEMM (guarded attention path: e1 AND e2 in one launch)
// ============================================================================
__device__ __forceinline__ unsigned long long pack2(float lo, float hi) {
    unsigned long long r;
    asm("mov.b64 %0, {%1, %2};" : "=l"(r) : "f"(lo), "f"(hi));
    return r;
}
__device__ __forceinline__ void unpack2(unsigned long long v, float& lo, float& hi) {
    asm("mov.b64 {%0, %1}, %2;" : "=f"(lo), "=f"(hi) : "l"(v));
}
__device__ __forceinline__ unsigned long long fma2(unsigned long long a,
                                                   unsigned long long b,
                                                   unsigned long long c) {
    unsigned long long d;
    asm("fma.rn.f32x2 %0, %1, %2, %3;" : "=l"(d) : "l"(a), "l"(b), "l"(c));
    return d;
}

#define BM 128
#define BN 128
#define BK 16
#define FPITCH 130

__global__ __launch_bounds__(256, 2)
void gemm_e1e2_kernel(const float* __restrict__ W1, const float* __restrict__ b1,
                      float* __restrict__ out1,
                      const float* __restrict__ W2, const float* __restrict__ b2,
                      float* __restrict__ out2,
                      const float* __restrict__ X,
                      const float* __restrict__ guard)
{
    if (__ldg(guard) == 0.0f) return;

    const bool second = blockIdx.y >= 2;
    const float* W    = second ? W2 : W1;
    const float* bias = second ? b2 : b1;
    float* out        = second ? out2 : out1;
    const int by      = second ? (int)blockIdx.y - 2 : (int)blockIdx.y;

    const int n  = blockIdx.z;
    const float* Xb = X  + (size_t)n * CCH * HWP;
    float*       Ob = out + (size_t)n * DCH * HWP;

    __shared__ unsigned long long As[BK * FPITCH];
    __shared__ float              Bs[BK * BN];

    const int tid = threadIdx.x;
    const int tx  = tid & 15;
    const int ty  = tid >> 4;
    const int o0  = by * BM;
    const int p0  = blockIdx.x * BN;

    unsigned long long acc[8][4];
    #pragma unroll
    for (int i = 0; i < 8; ++i)
        #pragma unroll
        for (int j = 0; j < 4; ++j) acc[i][j] = 0ULL;

    const int wr0 = tid >> 2;
    const int wc0 = (tid & 3) * 4;
    const int xk0 = tid >> 5;
    const int xc0 = (tid & 31) * 4;

    for (int k0 = 0; k0 < CCH; k0 += BK) {
        #pragma unroll
        for (int l = 0; l < 2; ++l) {
            const int r = wr0 + l * 64;
            const float4 v = *reinterpret_cast<const float4*>(
                &W[(size_t)(o0 + r) * CCH + k0 + wc0]);
            As[(wc0 + 0) * FPITCH + r] = pack2(v.x, v.x);
            As[(wc0 + 1) * FPITCH + r] = pack2(v.y, v.y);
            As[(wc0 + 2) * FPITCH + r] = pack2(v.z, v.z);
            As[(wc0 + 3) * FPITCH + r] = pack2(v.w, v.w);
        }
        #pragma unroll
        for (int l = 0; l < 2; ++l) {
            const int kk = xk0 + l * 8;
            const float4 v = *reinterpret_cast<const float4*>(
                &Xb[(size_t)(k0 + kk) * HWP + p0 + xc0]);
            *reinterpret_cast<float4*>(&Bs[kk * BN + xc0]) = v;
        }
        __syncthreads();

        #pragma unroll
        for (int kk = 0; kk < BK; ++kk) {
            unsigned long long a[8];
            const unsigned long long* arow = &As[kk * FPITCH + ty * 8];
            #pragma unroll
            for (int i = 0; i < 8; ++i) a[i] = arow[i];
            unsigned long long b[4];
            const unsigned long long* brow =
                reinterpret_cast<const unsigned long long*>(&Bs[kk * BN]) + tx * 4;
            #pragma unroll
            for (int j = 0; j < 4; ++j) b[j] = brow[j];
            #pragma unroll
            for (int i = 0; i < 8; ++i)
                #pragma unroll
                for (int j = 0; j < 4; ++j)
                    acc[i][j] = fma2(a[i], b[j], acc[i][j]);
        }
        __syncthreads();
    }

    #pragma unroll
    for (int i = 0; i < 8; ++i) {
        const int o = o0 + ty * 8 + i;
        const float bvv = __ldg(&bias[o]);
        float* orow = &Ob[(size_t)o * HWP + p0 + tx * 8];
        #pragma unroll
        for (int j = 0; j < 4; ++j) {
            float lo, hi;
            unpack2(acc[i][j], lo, hi);
            float2 r;
            r.x = fmaxf(lo + bvv, 0.0f);
            r.y = fmaxf(hi + bvv, 0.0f);
            *reinterpret_cast<float2*>(&orow[2 * j]) = r;
        }
    }
}

// ============================================================================
// Attention fallback (guarded): scores + softmax
// ============================================================================
__global__ __launch_bounds__(256)
void attn_softmax_kernel(const float* __restrict__ alpha)
{
    if (__ldg(alpha) == 0.0f) return;

    __shared__ float e1col[DCH];
    __shared__ float red[256];
    const int tid = threadIdx.x;

    for (int row = blockIdx.x; row < NB * HWP; row += gridDim.x) {
        const int n = row >> 12;
        const int i = row & (HWP - 1);
        const float* e1n = g_e1 + (size_t)n * DCH * HWP;
        const float* e2n = g_e2 + (size_t)n * DCH * HWP;
        float* arow = g_attn + (size_t)n * HWP * HWP + (size_t)i * HWP;

        e1col[tid] = e1n[(size_t)tid * HWP + i];
        __syncthreads();

        float sc[16];
        float mx = -3.4e38f;
        #pragma unroll 1
        for (int jj = 0; jj < 16; ++jj) {
            const int j = jj * 256 + tid;
            float s = 0.0f;
            for (int d = 0; d < DCH; ++d) s += e1col[d] * e2n[(size_t)d * HWP + j];
            sc[jj] = s;
            mx = fmaxf(mx, s);
        }
        red[tid] = mx; __syncthreads();
        for (int s = 128; s > 0; s >>= 1) {
            if (tid < s) red[tid] = fmaxf(red[tid], red[tid + s]);
            __syncthreads();
        }
        mx = red[0]; __syncthreads();

        float sum = 0.0f;
        #pragma unroll
        for (int jj = 0; jj < 16; ++jj) { sc[jj] = expf(sc[jj] - mx); sum += sc[jj]; }
        red[tid] = sum; __syncthreads();
        for (int s = 128; s > 0; s >>= 1) {
            if (tid < s) red[tid] += red[tid + s];
            __syncthreads();
        }
        const float inv = 1.0f / red[0];
        __syncthreads();

        #pragma unroll
        for (int jj = 0; jj < 16; ++jj) arow[jj * 256 + tid] = sc[jj] * inv;
        __syncthreads();
    }
}

// ============================================================================
// Attention fallback bmm (guarded)
// ============================================================================
__global__ __launch_bounds__(256)
void bmm_alpha_kernel(const float* __restrict__ x, float* __restrict__ out,
                      const float* __restrict__ alpha_p)
{
    const float alpha = __ldg(alpha_p);
    if (alpha == 0.0f) return;

    __shared__ float xs[HWP];
    const int tid = threadIdx.x;

    for (int row = blockIdx.x; row < NB * CCH; row += gridDim.x) {
        const int n = row >> 11;
        const int c = row & (CCH - 1);
        const float* xr = x + ((size_t)n * CCH + c) * HWP;
        const float* an = g_attn + (size_t)n * HWP * HWP;
        float* orow = out + ((size_t)n * CCH + c) * HWP;

        for (int j = tid; j < HWP; j += 256) xs[j] = xr[j];
        __syncthreads();

        for (int i = tid; i < HWP; i += 256) {
            float acc = 0.0f;
            const float* ai = an + (size_t)i * HWP;
            for (int j = 0; j < HWP; ++j) acc += xs[j] * ai[j];
            orow[i] += alpha * acc;
        }
        __syncthreads();
    }
}

// ============================================================================
// launch (5 launches/iter)
// ============================================================================
extern "C" void kernel_launch(void* const* d_in, const int* in_sizes, int n_in,
                              void* d_out, int out_size)
{
    const float* x     = (const float*)d_in[0];
    const float* w1    = (const float*)d_in[1];
    const float* b1    = (const float*)d_in[2];
    const float* w2    = (const float*)d_in[3];
    const float* b2    = (const float*)d_in[4];
    const float* w3    = (const float*)d_in[5];
    const float* b3    = (const float*)d_in[6];
    const float* alpha = (const float*)d_in[7];
    float* out = (float*)d_out;

    float *e1p = nullptr, *e2p = nullptr;
    __half *w3h = nullptr, *xth = nullptr;
    cudaGetSymbolAddress((void**)&e1p, g_e1);
    cudaGetSymbolAddress((void**)&e2p, g_e2);
    cudaGetSymbolAddress((void**)&w3h, g_w3h);
    cudaGetSymbolAddress((void**)&xth, g_xth);

    static bool attr_done = false;
    if (!attr_done) {
        cudaFuncSetAttribute(gemm_f16_bias_relu,
                             cudaFuncAttributeMaxDynamicSharedMemorySize,
                             GEMM_DSMEM);
        attr_done = true;
    }

    // 0: fused pre-pass: X -> fp16 X^T, W3 -> fp16
    prepass_kernel<<<dim3(128, 32, NB + 1), 256>>>(
        x, xth, (const float4*)w3, (uint2*)w3h);
    // 1: guarded e1+e2 GEMMs (early-exit on alpha == 0)
    gemm_e1e2_kernel<<<dim3(HWP / BN, 4, NB), 256>>>(
        w1, b1, e1p, w2, b2, e2p, x, alpha);
    // 2: guarded softmax
    attn_softmax_kernel<<<2048, 256>>>(alpha);
    // 3: assembly = relu(w3 @ x + b3) -> d_out (fp16 TC, anti-phase warps)
    gemm_f16_bias_relu<<<dim3(HWP / HTN, CCH / HTM, NB), 128, GEMM_DSMEM>>>(
        w3h, xth, b3, out);
    // 4: guarded bmm (out += alpha * x @ attn^T)
    bmm_alpha_kernel<<<1024, 256>>>(x, out, alpha);
}

// round 15
// speedup vs baseline: 5.4171x; 5.4171x over previous
#include <cuda_runtime.h>
#include <cuda_bf16.h>
#include <cuda_fp16.h>
#include <cstdint>

// ============================================================================
// NonLocalPositionAttention
//   y = alpha * (x @ softmax(e1^T e2)^T) + relu(w3 @ x + b3)
// alpha == 0 for benchmark inputs -> y == relu(w3 @ x + b3).
// Assembly GEMM: mma.sync m16n8k16 fp16 (fp32 acc). R15 = R12 (64x64 warp
// tiles, 4 warps/CTA, 3-stage cp.async, 3 CTAs/SM) + COMPILE-TIME-SAFE
// anti-phase: odd-wn warps traverse k-steps in reverse (ks = ksi ^ wn). The
// R14 version additionally reversed the mi loop, which made acc[] runtime-
// indexed -> local-memory spills (regs 168 + L1 85% + 5x regression). Here
// acc indices stay static. Attention branch guarded.
// ============================================================================

#define NB   4
#define CCH  2048
#define DCH  256
#define HWP  4096

// ---- scratch ---------------------------------------------------------------
__device__ float  g_e1[(size_t)NB * DCH * HWP];
__device__ float  g_e2[(size_t)NB * DCH * HWP];
__device__ float  g_attn[(size_t)NB * HWP * HWP];
__device__ __half g_w3h[(size_t)CCH * CCH];           // fp16 W3 [o][k]
__device__ __half g_xth[(size_t)NB * HWP * CCH];      // fp16 X^T [n][p][k]

// ============================================================================
// helpers
// ============================================================================
__device__ __forceinline__ uint32_t smem_u32(const void* p) {
    uint32_t a;
    asm("{ .reg .u64 t; cvta.to.shared.u64 t, %1; cvt.u32.u64 %0, t; }"
        : "=r"(a) : "l"(p));
    return a;
}
__device__ __forceinline__ void cp_async16(uint32_t dst, const void* src) {
    asm volatile("cp.async.cg.shared.global [%0], [%1], 16;"
                 :: "r"(dst), "l"(src) : "memory");
}
#define CP_COMMIT() asm volatile("cp.async.commit_group;" ::: "memory")
#define CP_WAIT1()  asm volatile("cp.async.wait_group 1;" ::: "memory")

__device__ __forceinline__ void mma_f16(float* d, const uint32_t* a,
                                        const uint32_t* b) {
    asm volatile(
        "mma.sync.aligned.m16n8k16.row.col.f32.f16.f16.f32 "
        "{%0,%1,%2,%3}, {%4,%5,%6,%7}, {%8,%9}, {%0,%1,%2,%3};"
        : "+f"(d[0]), "+f"(d[1]), "+f"(d[2]), "+f"(d[3])
        : "r"(a[0]), "r"(a[1]), "r"(a[2]), "r"(a[3]), "r"(b[0]), "r"(b[1]));
}

// ============================================================================
// fused pre-pass: z<NB -> X transpose->fp16; z==NB -> W3 ->fp16
// ============================================================================
__global__ void __launch_bounds__(256)
prepass_kernel(const float* __restrict__ x, __half* __restrict__ xt,
               const float4* __restrict__ w3, uint2* __restrict__ w3h)
{
    const int tid = threadIdx.x;
    if (blockIdx.z < NB) {
        __shared__ float t[32][65];   // [p_local][c_local]
        const int n  = blockIdx.z;
        const int c0 = blockIdx.y * 64;
        const int p0 = blockIdx.x * 32;

        const float* xb = x + (size_t)n * CCH * HWP;
        __half* xtb = xt + (size_t)n * HWP * CCH;

        {
            const int p_l = tid & 31;
            #pragma unroll
            for (int i = 0; i < 8; ++i) {
                const int c_l = (tid >> 5) + i * 8;
                t[p_l][c_l] = xb[(size_t)(c0 + c_l) * HWP + p0 + p_l];
            }
        }
        __syncthreads();
        {
            const int cp = tid & 31;
            #pragma unroll
            for (int i = 0; i < 4; ++i) {
                const int p_l = (tid >> 5) + i * 8;
                __half2 v = __floats2half2_rn(t[p_l][2 * cp], t[p_l][2 * cp + 1]);
                *reinterpret_cast<__half2*>(
                    &xtb[(size_t)(p0 + p_l) * CCH + c0 + 2 * cp]) = v;
            }
        }
    } else {
        const int i = (blockIdx.y * 128 + blockIdx.x) * 256 + tid;
        const float4 v = w3[i];
        __half2 lo = __floats2half2_rn(v.x, v.y);
        __half2 hi = __floats2half2_rn(v.z, v.w);
        uint2 o;
        o.x = *reinterpret_cast<uint32_t*>(&lo);
        o.y = *reinterpret_cast<uint32_t*>(&hi);
        w3h[i] = o;
    }
}

// ============================================================================
// fp16 tensor-core GEMM + bias + relu (fp32 accumulate):
//   out[n,o,p] = relu( sum_c W[o,c] * X[n,c,p] + bias[o] )
// CTA tile 128x128x32; 4 warps (2m x 2n), warp tile 64x64.
// ks order flipped for odd wn (static acc indexing preserved).
// A/B smem rows pitch 20 words (conflict-free). 3-stage ring, 3 CTAs/SM.
// ============================================================================
#define HTM 128
#define HTN 128
#define HTK 32
#define H_NSLABS (CCH / HTK)                 // 64
#define HPITCH_B 80                          // bytes per smem row
#define A_STAGE (HTM * HPITCH_B)             // 10240
#define B_STAGE (HTN * HPITCH_B)             // 10240
#define STAGE_B (A_STAGE + B_STAGE)          // 20480
#define NSTAGE 3
#define GEMM_DSMEM (NSTAGE * STAGE_B)        // 61440

__global__ void __launch_bounds__(128, 3)
gemm_f16_bias_relu(const __half* __restrict__ Wh, const __half* __restrict__ Xth,
                   const float* __restrict__ bias, float* __restrict__ out)
{
    extern __shared__ char smem[];
    const uint32_t smem_base = smem_u32(smem);

    const int tid  = threadIdx.x;
    const int wid  = tid >> 5;
    const int lane = tid & 31;
    const int g    = lane >> 2;
    const int tig  = lane & 3;
    const int wm   = wid >> 1;     // 0..1
    const int wn   = wid & 1;      // 0..1

    const int n  = blockIdx.z;
    const int o0 = blockIdx.y * HTM;
    const int p0 = blockIdx.x * HTN;
    const __half* Xb = Xth + (size_t)n * HWP * CCH;
    float*        Ob = out + (size_t)n * CCH * HWP;

    float acc[4][8][4];
    #pragma unroll
    for (int mi = 0; mi < 4; ++mi)
        #pragma unroll
        for (int ni = 0; ni < 8; ++ni)
            #pragma unroll
            for (int q = 0; q < 4; ++q) acc[mi][ni][q] = 0.0f;

    const int cp_row = tid >> 2, cp_cw = tid & 3;

    #define ISSUE_SLAB(S, BUF) do {                                           \
        const int _k0 = (S) * HTK;                                            \
        const uint32_t _dA = smem_base + (BUF) * STAGE_B;                     \
        const uint32_t _dB = _dA + A_STAGE;                                   \
        _Pragma("unroll")                                                     \
        for (int j = 0; j < 4; ++j) {                                         \
            const int row = cp_row + j * 32;                                  \
            cp_async16(_dA + row * HPITCH_B + cp_cw * 16,                     \
                       &Wh[(size_t)(o0 + row) * CCH + _k0 + cp_cw * 8]);      \
        }                                                                     \
        _Pragma("unroll")                                                     \
        for (int j = 0; j < 4; ++j) {                                         \
            const int row = cp_row + j * 32;                                  \
            cp_async16(_dB + row * HPITCH_B + cp_cw * 16,                     \
                       &Xb[(size_t)(p0 + row) * CCH + _k0 + cp_cw * 8]);      \
        }                                                                     \
    } while (0)

    ISSUE_SLAB(0, 0); CP_COMMIT();
    ISSUE_SLAB(1, 1); CP_COMMIT();

    for (int s = 0; s < H_NSLABS; ++s) {
        CP_WAIT1();
        __syncthreads();
        if (s + 2 < H_NSLABS) ISSUE_SLAB(s + 2, (s + 2) % NSTAGE);
        CP_COMMIT();

        const uint32_t* As = reinterpret_cast<const uint32_t*>(
            smem + (s % NSTAGE) * STAGE_B);
        const uint32_t* Bs = reinterpret_cast<const uint32_t*>(
            smem + (s % NSTAGE) * STAGE_B + A_STAGE);

        #pragma unroll
        for (int ksi = 0; ksi < 2; ++ksi) {
            const int ks = ksi ^ wn;          // odd-wn warps: reverse k order
                                              // (acc indices stay static)
            const int kw = ks * 8 + tig;      // word index within 20-word row
            uint32_t b[8][2];
            #pragma unroll
            for (int ni = 0; ni < 8; ++ni) {
                const int col = wn * 64 + ni * 8 + g;
                b[ni][0] = Bs[col * 20 + kw];
                b[ni][1] = Bs[col * 20 + kw + 4];
            }
            #pragma unroll
            for (int mi = 0; mi < 4; ++mi) {
                const int m = wm * 64 + mi * 16;
                uint32_t a[4];
                a[0] = As[(m + g) * 20 + kw];
                a[1] = As[(m + 8 + g) * 20 + kw];
                a[2] = As[(m + g) * 20 + kw + 4];
                a[3] = As[(m + 8 + g) * 20 + kw + 4];
                #pragma unroll
                for (int ni = 0; ni < 8; ++ni)
                    mma_f16(acc[mi][ni], a, b[ni]);
            }
        }
    }

    // ---- epilogue: bias + relu -> GMEM ----
    #pragma unroll
    for (int mi = 0; mi < 4; ++mi) {
        const int row_lo = o0 + wm * 64 + mi * 16 + g;
        const int row_hi = row_lo + 8;
        const float blo = __ldg(&bias[row_lo]);
        const float bhi = __ldg(&bias[row_hi]);
        float* plo = &Ob[(size_t)row_lo * HWP + p0 + wn * 64 + tig * 2];
        float* phi = &Ob[(size_t)row_hi * HWP + p0 + wn * 64 + tig * 2];
        #pragma unroll
        for (int ni = 0; ni < 8; ++ni) {
            float2 vlo, vhi;
            vlo.x = fmaxf(acc[mi][ni][0] + blo, 0.0f);
            vlo.y = fmaxf(acc[mi][ni][1] + blo, 0.0f);
            vhi.x = fmaxf(acc[mi][ni][2] + bhi, 0.0f);
            vhi.y = fmaxf(acc[mi][ni][3] + bhi, 0.0f);
            *reinterpret_cast<float2*>(&plo[ni * 8]) = vlo;
            *reinterpret_cast<float2*>(&phi[ni * 8]) = vhi;
        }
    }
}

// ============================================================================
// FFMA2 SGEMM (guarded attention path: e1 AND e2 in one launch)
// ============================================================================
__device__ __forceinline__ unsigned long long pack2(float lo, float hi) {
    unsigned long long r;
    asm("mov.b64 %0, {%1, %2};" : "=l"(r) : "f"(lo), "f"(hi));
    return r;
}
__device__ __forceinline__ void unpack2(unsigned long long v, float& lo, float& hi) {
    asm("mov.b64 {%0, %1}, %2;" : "=f"(lo), "=f"(hi) : "l"(v));
}
__device__ __forceinline__ unsigned long long fma2(unsigned long long a,
                                                   unsigned long long b,
                                                   unsigned long long c) {
    unsigned long long d;
    asm("fma.rn.f32x2 %0, %1, %2, %3;" : "=l"(d) : "l"(a), "l"(b), "l"(c));
    return d;
}

#define BM 128
#define BN 128
#define BK 16
#define FPITCH 130

__global__ __launch_bounds__(256, 2)
void gemm_e1e2_kernel(const float* __restrict__ W1, const float* __restrict__ b1,
                      float* __restrict__ out1,
                      const float* __restrict__ W2, const float* __restrict__ b2,
                      float* __restrict__ out2,
                      const float* __restrict__ X,
                      const float* __restrict__ guard)
{
    if (__ldg(guard) == 0.0f) return;

    const bool second = blockIdx.y >= 2;
    const float* W    = second ? W2 : W1;
    const float* bias = second ? b2 : b1;
    float* out        = second ? out2 : out1;
    const int by      = second ? (int)blockIdx.y - 2 : (int)blockIdx.y;

    const int n  = blockIdx.z;
    const float* Xb = X  + (size_t)n * CCH * HWP;
    float*       Ob = out + (size_t)n * DCH * HWP;

    __shared__ unsigned long long As[BK * FPITCH];
    __shared__ float              Bs[BK * BN];

    const int tid = threadIdx.x;
    const int tx  = tid & 15;
    const int ty  = tid >> 4;
    const int o0  = by * BM;
    const int p0  = blockIdx.x * BN;

    unsigned long long acc[8][4];
    #pragma unroll
    for (int i = 0; i < 8; ++i)
        #pragma unroll
        for (int j = 0; j < 4; ++j) acc[i][j] = 0ULL;

    const int wr0 = tid >> 2;
    const int wc0 = (tid & 3) * 4;
    const int xk0 = tid >> 5;
    const int xc0 = (tid & 31) * 4;

    for (int k0 = 0; k0 < CCH; k0 += BK) {
        #pragma unroll
        for (int l = 0; l < 2; ++l) {
            const int r = wr0 + l * 64;
            const float4 v = *reinterpret_cast<const float4*>(
                &W[(size_t)(o0 + r) * CCH + k0 + wc0]);
            As[(wc0 + 0) * FPITCH + r] = pack2(v.x, v.x);
            As[(wc0 + 1) * FPITCH + r] = pack2(v.y, v.y);
            As[(wc0 + 2) * FPITCH + r] = pack2(v.z, v.z);
            As[(wc0 + 3) * FPITCH + r] = pack2(v.w, v.w);
        }
        #pragma unroll
        for (int l = 0; l < 2; ++l) {
            const int kk = xk0 + l * 8;
            const float4 v = *reinterpret_cast<const float4*>(
                &Xb[(size_t)(k0 + kk) * HWP + p0 + xc0]);
            *reinterpret_cast<float4*>(&Bs[kk * BN + xc0]) = v;
        }
        __syncthreads();

        #pragma unroll
        for (int kk = 0; kk < BK; ++kk) {
            unsigned long long a[8];
            const unsigned long long* arow = &As[kk * FPITCH + ty * 8];
            #pragma unroll
            for (int i = 0; i < 8; ++i) a[i] = arow[i];
            unsigned long long b[4];
            const unsigned long long* brow =
                reinterpret_cast<const unsigned long long*>(&Bs[kk * BN]) + tx * 4;
            #pragma unroll
            for (int j = 0; j < 4; ++j) b[j] = brow[j];
            #pragma unroll
            for (int i = 0; i < 8; ++i)
                #pragma unroll
                for (int j = 0; j < 4; ++j)
                    acc[i][j] = fma2(a[i], b[j], acc[i][j]);
        }
        __syncthreads();
    }

    #pragma unroll
    for (int i = 0; i < 8; ++i) {
        const int o = o0 + ty * 8 + i;
        const float bvv = __ldg(&bias[o]);
        float* orow = &Ob[(size_t)o * HWP + p0 + tx * 8];
        #pragma unroll
        for (int j = 0; j < 4; ++j) {
            float lo, hi;
            unpack2(acc[i][j], lo, hi);
            float2 r;
            r.x = fmaxf(lo + bvv, 0.0f);
            r.y = fmaxf(hi + bvv, 0.0f);
            *reinterpret_cast<float2*>(&orow[2 * j]) = r;
        }
    }
}

// ============================================================================
// Attention fallback (guarded): scores + softmax
// ============================================================================
__global__ __launch_bounds__(256)
void attn_softmax_kernel(const float* __restrict__ alpha)
{
    if (__ldg(alpha) == 0.0f) return;

    __shared__ float e1col[DCH];
    __shared__ float red[256];
    const int tid = threadIdx.x;

    for (int row = blockIdx.x; row < NB * HWP; row += gridDim.x) {
        const int n = row >> 12;
        const int i = row & (HWP - 1);
        const float* e1n = g_e1 + (size_t)n * DCH * HWP;
        const float* e2n = g_e2 + (size_t)n * DCH * HWP;
        float* arow = g_attn + (size_t)n * HWP * HWP + (size_t)i * HWP;

        e1col[tid] = e1n[(size_t)tid * HWP + i];
        __syncthreads();

        float sc[16];
        float mx = -3.4e38f;
        #pragma unroll 1
        for (int jj = 0; jj < 16; ++jj) {
            const int j = jj * 256 + tid;
            float s = 0.0f;
            for (int d = 0; d < DCH; ++d) s += e1col[d] * e2n[(size_t)d * HWP + j];
            sc[jj] = s;
            mx = fmaxf(mx, s);
        }
        red[tid] = mx; __syncthreads();
        for (int s = 128; s > 0; s >>= 1) {
            if (tid < s) red[tid] = fmaxf(red[tid], red[tid + s]);
            __syncthreads();
        }
        mx = red[0]; __syncthreads();

        float sum = 0.0f;
        #pragma unroll
        for (int jj = 0; jj < 16; ++jj) { sc[jj] = expf(sc[jj] - mx); sum += sc[jj]; }
        red[tid] = sum; __syncthreads();
        for (int s = 128; s > 0; s >>= 1) {
            if (tid < s) red[tid] += red[tid + s];
            __syncthreads();
        }
        const float inv = 1.0f / red[0];
        __syncthreads();

        #pragma unroll
        for (int jj = 0; jj < 16; ++jj) arow[jj * 256 + tid] = sc[jj] * inv;
        __syncthreads();
    }
}

// ============================================================================
// Attention fallback bmm (guarded)
// ============================================================================
__global__ __launch_bounds__(256)
void bmm_alpha_kernel(const float* __restrict__ x, float* __restrict__ out,
                      const float* __restrict__ alpha_p)
{
    const float alpha = __ldg(alpha_p);
    if (alpha == 0.0f) return;

    __shared__ float xs[HWP];
    const int tid = threadIdx.x;

    for (int row = blockIdx.x; row < NB * CCH; row += gridDim.x) {
        const int n = row >> 11;
        const int c = row & (CCH - 1);
        const float* xr = x + ((size_t)n * CCH + c) * HWP;
        const float* an = g_attn + (size_t)n * HWP * HWP;
        float* orow = out + ((size_t)n * CCH + c) * HWP;

        for (int j = tid; j < HWP; j += 256) xs[j] = xr[j];
        __syncthreads();

        for (int i = tid; i < HWP; i += 256) {
            float acc = 0.0f;
            const float* ai = an + (size_t)i * HWP;
            for (int j = 0; j < HWP; ++j) acc += xs[j] * ai[j];
            orow[i] += alpha * acc;
        }
        __syncthreads();
    }
}

// ============================================================================
// launch (5 launches/iter)
// ============================================================================
extern "C" void kernel_launch(void* const* d_in, const int* in_sizes, int n_in,
                              void* d_out, int out_size)
{
    const float* x     = (const float*)d_in[0];
    const float* w1    = (const float*)d_in[1];
    const float* b1    = (const float*)d_in[2];
    const float* w2    = (const float*)d_in[3];
    const float* b2    = (const float*)d_in[4];
    const float* w3    = (const float*)d_in[5];
    const float* b3    = (const float*)d_in[6];
    const float* alpha = (const float*)d_in[7];
    float* out = (float*)d_out;

    float *e1p = nullptr, *e2p = nullptr;
    __half *w3h = nullptr, *xth = nullptr;
    cudaGetSymbolAddress((void**)&e1p, g_e1);
    cudaGetSymbolAddress((void**)&e2p, g_e2);
    cudaGetSymbolAddress((void**)&w3h, g_w3h);
    cudaGetSymbolAddress((void**)&xth, g_xth);

    static bool attr_done = false;
    if (!attr_done) {
        cudaFuncSetAttribute(gemm_f16_bias_relu,
                             cudaFuncAttributeMaxDynamicSharedMemorySize,
                             GEMM_DSMEM);
        attr_done = true;
    }

    // 0: fused pre-pass: X -> fp16 X^T, W3 -> fp16
    prepass_kernel<<<dim3(128, 32, NB + 1), 256>>>(
        x, xth, (const float4*)w3, (uint2*)w3h);
    // 1: guarded e1+e2 GEMMs (early-exit on alpha == 0)
    gemm_e1e2_kernel<<<dim3(HWP / BN, 4, NB), 256>>>(
        w1, b1, e1p, w2, b2, e2p, x, alpha);
    // 2: guarded softmax
    attn_softmax_kernel<<<2048, 256>>>(alpha);
    // 3: assembly = relu(w3 @ x + b3) -> d_out (fp16 TC, safe anti-phase ks)
    gemm_f16_bias_relu<<<dim3(HWP / HTN, CCH / HTM, NB), 128, GEMM_DSMEM>>>(
        w3h, xth, b3, out);
    // 4: guarded bmm (out += alpha * x @ attn^T)
    bmm_alpha_kernel<<<1024, 256>>>(x, out, alpha);
}